// round 1
// baseline (speedup 1.0000x reference)
#include <cuda_runtime.h>
#include <math.h>

// Problem constants
constexpr int Bc   = 2;
constexpr int T    = 2048;
constexpr int DIM  = 2048;
constexpr int H    = 16;
constexpr int HKV  = 4;
constexpr int D    = 128;
constexpr int HALF = 64;
constexpr int G    = 4;      // H / HKV
constexpr int BT   = Bc * T; // 4096
constexpr int KVD  = HKV * D; // 512

// Scratch (allocation-free rule: __device__ globals)
__device__ float g_q[(size_t)BT * DIM];
__device__ float g_k[(size_t)BT * KVD];
__device__ float g_v[(size_t)BT * KVD];
__device__ float g_y[(size_t)BT * DIM];
__device__ float g_cos[T * HALF];
__device__ float g_sin[T * HALF];

// ---------------------------------------------------------------------------
// RoPE tables. T > TRAIN_LEN -> scale = 2, base = 10000 * 2^(D/(D-2)).
// numpy computes inv_freq/cos/sin in float64 then casts; match with doubles.
// ---------------------------------------------------------------------------
__global__ void rope_table_kernel() {
    int idx = blockIdx.x * blockDim.x + threadIdx.x;
    if (idx >= T * HALF) return;
    int t = idx / HALF, i = idx % HALF;
    double base = 10000.0 * pow(2.0, 128.0 / 126.0);
    double inv  = pow(base, -(2.0 * (double)i) / 128.0);
    double f    = (double)t * inv;
    g_cos[idx] = (float)cos(f);
    g_sin[idx] = (float)sin(f);
}

// ---------------------------------------------------------------------------
// NT SGEMM: C[m,n] = sum_k A[m,k] * B[n,k]   (both row-major, K-major)
// BM=BN=128, BK=8, 256 threads, 8x8 per-thread microtile.
// Requires M,N % 128 == 0, K % 8 == 0 (true for all our shapes).
// ---------------------------------------------------------------------------
__global__ void __launch_bounds__(256) sgemm_nt_kernel(
    const float* __restrict__ A, const float* __restrict__ Bm,
    float* __restrict__ C, int M, int N, int K)
{
    __shared__ float As[8][128];
    __shared__ float Bs[8][128];
    int tid = threadIdx.x;
    int bm = blockIdx.y * 128, bn = blockIdx.x * 128;
    int tx = tid & 15, ty = tid >> 4;
    int lrow = tid >> 1, lseg = (tid & 1) * 4;

    float acc[8][8];
    #pragma unroll
    for (int i = 0; i < 8; i++)
        #pragma unroll
        for (int j = 0; j < 8; j++) acc[i][j] = 0.f;

    for (int k0 = 0; k0 < K; k0 += 8) {
        float4 av = *(const float4*)&A [(size_t)(bm + lrow) * K + k0 + lseg];
        float4 bv = *(const float4*)&Bm[(size_t)(bn + lrow) * K + k0 + lseg];
        As[lseg + 0][lrow] = av.x; As[lseg + 1][lrow] = av.y;
        As[lseg + 2][lrow] = av.z; As[lseg + 3][lrow] = av.w;
        Bs[lseg + 0][lrow] = bv.x; Bs[lseg + 1][lrow] = bv.y;
        Bs[lseg + 2][lrow] = bv.z; Bs[lseg + 3][lrow] = bv.w;
        __syncthreads();
        #pragma unroll
        for (int kk = 0; kk < 8; kk++) {
            float4 a0 = *(const float4*)&As[kk][ty * 8];
            float4 a1 = *(const float4*)&As[kk][ty * 8 + 4];
            float4 b0 = *(const float4*)&Bs[kk][tx * 8];
            float4 b1 = *(const float4*)&Bs[kk][tx * 8 + 4];
            float ar[8] = {a0.x, a0.y, a0.z, a0.w, a1.x, a1.y, a1.z, a1.w};
            float br[8] = {b0.x, b0.y, b0.z, b0.w, b1.x, b1.y, b1.z, b1.w};
            #pragma unroll
            for (int i = 0; i < 8; i++)
                #pragma unroll
                for (int j = 0; j < 8; j++)
                    acc[i][j] += ar[i] * br[j];
        }
        __syncthreads();
    }
    #pragma unroll
    for (int i = 0; i < 8; i++) {
        float4 v0 = make_float4(acc[i][0], acc[i][1], acc[i][2], acc[i][3]);
        float4 v1 = make_float4(acc[i][4], acc[i][5], acc[i][6], acc[i][7]);
        size_t base = (size_t)(bm + ty * 8 + i) * N + bn + tx * 8;
        *(float4*)&C[base]     = v0;
        *(float4*)&C[base + 4] = v1;
    }
}

// ---------------------------------------------------------------------------
// Fused RMSNorm + RoPE (+ optional gain). One block per (token-row, head).
// buf layout: [BT][nheads*D], head h at column offset h*D.
// ---------------------------------------------------------------------------
__global__ void rmsrope_kernel(float* __restrict__ buf, int nheads,
                               const float* __restrict__ gain)
{
    int bt = blockIdx.x, h = blockIdx.y, tid = threadIdx.x; // 128 threads
    float* row = buf + (size_t)bt * nheads * D + h * D;
    float x = row[tid];
    float ss = x * x;
    #pragma unroll
    for (int o = 16; o; o >>= 1) ss += __shfl_xor_sync(0xffffffffu, ss, o);
    __shared__ float ws[4];
    __shared__ float sh[128];
    if ((tid & 31) == 0) ws[tid >> 5] = ss;
    __syncthreads();
    float total = ws[0] + ws[1] + ws[2] + ws[3];
    float rn = rsqrtf(total * (1.0f / 128.0f) + 1.1920929e-7f);
    sh[tid] = x * rn;
    __syncthreads();
    if (tid < HALF) {
        int t = bt % T;
        float c = g_cos[t * HALF + tid], s = g_sin[t * HALF + tid];
        float gv = gain ? gain[h] : 1.0f;
        float x1 = sh[tid], x2 = sh[tid + HALF];
        row[tid]        = (x1 * c + x2 * s) * gv;
        row[tid + HALF] = (x2 * c - x1 * s) * gv;
    }
}

// ---------------------------------------------------------------------------
// Flash attention (causal, GQA). Block = (64-query tile, head, batch).
// 256 threads: tr = tid/16 (0..15), tc = tid%16.
//  S phase: 4x4 microtile, rows i*16+tr, cols j*16+tc.
//  PV phase: 4x8 microtile, dims k*16+tc.
// smem padded strides 129 / 65 for conflict-free access.
// ---------------------------------------------------------------------------
constexpr int QS_STR = 129;
constexpr int PS_STR = 65;
constexpr size_t ATTN_SMEM = (size_t)(3 * 64 * QS_STR + 64 * PS_STR) * sizeof(float);

__global__ void __launch_bounds__(256) attn_kernel()
{
    extern __shared__ float sm[];
    float* Qs = sm;
    float* Ks = Qs + 64 * QS_STR;
    float* Vs = Ks + 64 * QS_STR;
    float* Ps = Vs + 64 * QS_STR;

    int qt = blockIdx.x, h = blockIdx.y, b = blockIdx.z;
    int hk = h / G;
    int tid = threadIdx.x;
    int tr = tid >> 4, tc = tid & 15;
    int qb = qt * 64;
    const float scale = 0.08838834764831845f; // 1/sqrt(128)

    const float* qptr = g_q + (size_t)(b * T + qb) * DIM + h * D;
    for (int i = tid; i < 64 * 128; i += 256) {
        int rr = i >> 7, cc = i & 127;
        Qs[rr * QS_STR + cc] = qptr[(size_t)rr * DIM + cc];
    }

    float m[4], l[4], acc[4][8];
    #pragma unroll
    for (int i = 0; i < 4; i++) {
        m[i] = -1e30f; l[i] = 0.f;
        #pragma unroll
        for (int k = 0; k < 8; k++) acc[i][k] = 0.f;
    }

    for (int j = 0; j <= qt; j++) {
        int kb = j * 64;
        const float* kp = g_k + (size_t)(b * T + kb) * KVD + hk * D;
        const float* vp = g_v + (size_t)(b * T + kb) * KVD + hk * D;
        __syncthreads(); // prior PV reads of Ks/Vs/Ps done (also covers Q load)
        for (int i = tid; i < 64 * 128; i += 256) {
            int rr = i >> 7, cc = i & 127;
            Ks[rr * QS_STR + cc] = kp[(size_t)rr * KVD + cc];
            Vs[rr * QS_STR + cc] = vp[(size_t)rr * KVD + cc];
        }
        __syncthreads();

        float s[4][4];
        #pragma unroll
        for (int i = 0; i < 4; i++)
            #pragma unroll
            for (int jj = 0; jj < 4; jj++) s[i][jj] = 0.f;

        #pragma unroll 4
        for (int d = 0; d < 128; d++) {
            float qv[4], kv[4];
            #pragma unroll
            for (int i = 0; i < 4; i++)  qv[i]  = Qs[(i * 16 + tr) * QS_STR + d];
            #pragma unroll
            for (int jj = 0; jj < 4; jj++) kv[jj] = Ks[(jj * 16 + tc) * QS_STR + d];
            #pragma unroll
            for (int i = 0; i < 4; i++)
                #pragma unroll
                for (int jj = 0; jj < 4; jj++)
                    s[i][jj] += qv[i] * kv[jj];
        }

        bool diag = (j == qt);
        #pragma unroll
        for (int i = 0; i < 4; i++)
            #pragma unroll
            for (int jj = 0; jj < 4; jj++) {
                float v = s[i][jj] * scale;
                if (diag && (jj * 16 + tc) > (i * 16 + tr)) v = -1e30f;
                s[i][jj] = v;
            }

        // online softmax per row (row statistics live in the 16-lane tc group)
        #pragma unroll
        for (int i = 0; i < 4; i++) {
            float mx = fmaxf(fmaxf(s[i][0], s[i][1]), fmaxf(s[i][2], s[i][3]));
            #pragma unroll
            for (int o = 1; o < 16; o <<= 1)
                mx = fmaxf(mx, __shfl_xor_sync(0xffffffffu, mx, o));
            float mn = fmaxf(m[i], mx);
            float f = expf(m[i] - mn);
            float sum = 0.f;
            #pragma unroll
            for (int jj = 0; jj < 4; jj++) {
                float p = expf(s[i][jj] - mn);
                s[i][jj] = p;
                sum += p;
            }
            #pragma unroll
            for (int o = 1; o < 16; o <<= 1)
                sum += __shfl_xor_sync(0xffffffffu, sum, o);
            l[i] = l[i] * f + sum;
            m[i] = mn;
            #pragma unroll
            for (int k = 0; k < 8; k++) acc[i][k] *= f;
            #pragma unroll
            for (int jj = 0; jj < 4; jj++)
                Ps[(i * 16 + tr) * PS_STR + jj * 16 + tc] = s[i][jj];
        }
        __syncthreads();

        // PV accumulate
        #pragma unroll 2
        for (int c = 0; c < 64; c++) {
            float pv[4], vv[8];
            #pragma unroll
            for (int i = 0; i < 4; i++) pv[i] = Ps[(i * 16 + tr) * PS_STR + c];
            #pragma unroll
            for (int k = 0; k < 8; k++) vv[k] = Vs[c * QS_STR + k * 16 + tc];
            #pragma unroll
            for (int i = 0; i < 4; i++)
                #pragma unroll
                for (int k = 0; k < 8; k++)
                    acc[i][k] += pv[i] * vv[k];
        }
    }

    float* yp = g_y + (size_t)(b * T + qb) * DIM + h * D;
    #pragma unroll
    for (int i = 0; i < 4; i++) {
        float inv = 1.0f / l[i];
        #pragma unroll
        for (int k = 0; k < 8; k++)
            yp[(size_t)(i * 16 + tr) * DIM + k * 16 + tc] = acc[i][k] * inv;
    }
}

// ---------------------------------------------------------------------------
extern "C" void kernel_launch(void* const* d_in, const int* in_sizes, int n_in,
                              void* d_out, int out_size)
{
    const float* x  = (const float*)d_in[0];
    const float* Wq = (const float*)d_in[1];
    const float* Wk = (const float*)d_in[2];
    const float* Wv = (const float*)d_in[3];
    const float* Wp = (const float*)d_in[4];
    const float* qg = (const float*)d_in[5];
    float* out = (float*)d_out;

    float *qp, *kp, *vp, *yp;
    cudaGetSymbolAddress((void**)&qp, g_q);
    cudaGetSymbolAddress((void**)&kp, g_k);
    cudaGetSymbolAddress((void**)&vp, g_v);
    cudaGetSymbolAddress((void**)&yp, g_y);

    rope_table_kernel<<<(T * HALF + 255) / 256, 256>>>();

    sgemm_nt_kernel<<<dim3(DIM / 128, BT / 128), 256>>>(x, Wq, qp, BT, DIM, DIM);
    sgemm_nt_kernel<<<dim3(KVD / 128, BT / 128), 256>>>(x, Wk, kp, BT, KVD, DIM);
    sgemm_nt_kernel<<<dim3(KVD / 128, BT / 128), 256>>>(x, Wv, vp, BT, KVD, DIM);

    rmsrope_kernel<<<dim3(BT, H),   128>>>(qp, H,   qg);
    rmsrope_kernel<<<dim3(BT, HKV), 128>>>(kp, HKV, nullptr);

    cudaFuncSetAttribute(attn_kernel, cudaFuncAttributeMaxDynamicSharedMemorySize,
                         (int)ATTN_SMEM);
    attn_kernel<<<dim3(T / 64, H, Bc), 256, ATTN_SMEM>>>();

    sgemm_nt_kernel<<<dim3(DIM / 128, BT / 128), 256>>>(yp, Wp, out, BT, DIM, DIM);
}

// round 3
// speedup vs baseline: 1.4558x; 1.4558x over previous
#include <cuda_runtime.h>
#include <cuda_bf16.h>
#include <math.h>
#include <stdint.h>

// Problem constants
constexpr int Bc   = 2;
constexpr int T    = 2048;
constexpr int DIM  = 2048;
constexpr int H    = 16;
constexpr int HKV  = 4;
constexpr int D    = 128;
constexpr int HALF = 64;
constexpr int G    = 4;
constexpr int BT   = Bc * T;   // 4096
constexpr int KVD  = HKV * D;  // 512
constexpr int K3   = 3 * DIM;  // 6144 (bf16x3 extended K)

// Scratch (__device__ globals; allocation-free rule)
__device__ float g_q[(size_t)BT * DIM];
__device__ float g_k[(size_t)BT * KVD];
__device__ float g_v[(size_t)BT * KVD];
__device__ float g_y[(size_t)BT * DIM];
__device__ float g_cos[T * HALF];
__device__ float g_sin[T * HALF];
__device__ __nv_bfloat16 g_xe [(size_t)BT  * K3];
__device__ __nv_bfloat16 g_ye [(size_t)BT  * K3];
__device__ __nv_bfloat16 g_wqe[(size_t)DIM * K3];
__device__ __nv_bfloat16 g_wke[(size_t)KVD * K3];
__device__ __nv_bfloat16 g_wve[(size_t)KVD * K3];
__device__ __nv_bfloat16 g_wpe[(size_t)DIM * K3];

// ---------------------------------------------------------------------------
// Helpers (sm_80-level features only: cp.async, ldmatrix, mma.sync bf16)
// ---------------------------------------------------------------------------
__device__ __forceinline__ uint32_t smem_u32(const void* p) {
    uint32_t a;
    asm("{ .reg .u64 t; cvta.to.shared.u64 t, %1; cvt.u32.u64 %0, t; }"
        : "=r"(a) : "l"(p));
    return a;
}
__device__ __forceinline__ void cpa16(uint32_t dst, const void* g) {
    asm volatile("cp.async.cg.shared.global [%0], [%1], 16;"
                 :: "r"(dst), "l"(g) : "memory");
}
#define CP_COMMIT() asm volatile("cp.async.commit_group;" ::: "memory")
#define CP_WAIT(n)  asm volatile("cp.async.wait_group %0;" :: "n"(n) : "memory")

__device__ __forceinline__ void ldm_x4(uint32_t& r0, uint32_t& r1,
                                       uint32_t& r2, uint32_t& r3, uint32_t a) {
    asm volatile("ldmatrix.sync.aligned.m8n8.x4.shared.b16 {%0,%1,%2,%3}, [%4];"
                 : "=r"(r0), "=r"(r1), "=r"(r2), "=r"(r3) : "r"(a));
}
__device__ __forceinline__ void mma16816(float* c, const uint32_t* a,
                                         uint32_t b0, uint32_t b1) {
    asm volatile(
        "mma.sync.aligned.m16n8k16.row.col.f32.bf16.bf16.f32 "
        "{%0,%1,%2,%3}, {%4,%5,%6,%7}, {%8,%9}, {%0,%1,%2,%3};"
        : "+f"(c[0]), "+f"(c[1]), "+f"(c[2]), "+f"(c[3])
        : "r"(a[0]), "r"(a[1]), "r"(a[2]), "r"(a[3]), "r"(b0), "r"(b1));
}

// ---------------------------------------------------------------------------
// RoPE tables (float64 to match numpy). T>TRAIN_LEN: base = 10000 * 2^(D/(D-2)).
// ---------------------------------------------------------------------------
__global__ void rope_table_kernel() {
    int idx = blockIdx.x * blockDim.x + threadIdx.x;
    if (idx >= T * HALF) return;
    int t = idx / HALF, i = idx % HALF;
    double base = 10000.0 * pow(2.0, 128.0 / 126.0);
    double inv  = pow(base, -(2.0 * (double)i) / 128.0);
    double f    = (double)t * inv;
    g_cos[idx] = (float)cos(f);
    g_sin[idx] = (float)sin(f);
}

// ---------------------------------------------------------------------------
// bf16x3 split: fp32 [rows, K] -> bf16 [rows, 3K].
// mode 0 (A side): [hi | lo | hi]    mode 1 (B side): [hi | hi | lo]
// One bf16 GEMM on extended operands = hi*hi + lo*hi + hi*lo  (fp32-class).
// ---------------------------------------------------------------------------
__global__ void split_kernel(const float* __restrict__ src,
                             __nv_bfloat16* __restrict__ dst,
                             int rows, int K, int mode) {
    long long idx = (long long)blockIdx.x * blockDim.x + threadIdx.x;
    long long total = (long long)rows * K;
    if (idx >= total) return;
    int r = (int)(idx / K), k = (int)(idx % K);
    float x = src[idx];
    __nv_bfloat16 h = __float2bfloat16(x);
    __nv_bfloat16 l = __float2bfloat16(x - __bfloat162float(h));
    __nv_bfloat16* row = dst + (size_t)r * (3 * K);
    if (mode == 0) { row[k] = h; row[K + k] = l; row[2 * K + k] = h; }
    else           { row[k] = h; row[K + k] = h; row[2 * K + k] = l; }
}

// ---------------------------------------------------------------------------
// bf16 NT GEMM via mma.sync (HMMA): C[m,n] = sum_k A[m,k]*B[n,k], fp32 acc.
// CTA 128x128, BK=32, 256 thr = 8 warps (4 M x 2 N), warp tile 32x64.
// cp.async double buffer; ldmatrix.x4 fragments; row pad 16B (conflict-free).
// Requires M%128==0, N%128==0, K%32==0.
// ---------------------------------------------------------------------------
constexpr int BK  = 32;
constexpr int LDS_ = BK + 8;   // 40 bf16 = 80 B row stride

__global__ void __launch_bounds__(256, 2) gemm_mma(
    const __nv_bfloat16* __restrict__ A, const __nv_bfloat16* __restrict__ B,
    float* __restrict__ C, int M, int N, int K)
{
    __shared__ __nv_bfloat16 As[2][128 * LDS_];
    __shared__ __nv_bfloat16 Bs[2][128 * LDS_];

    int tid = threadIdx.x, lane = tid & 31, wid = tid >> 5;
    int wm = wid & 3, wn = wid >> 2;           // warp coords: 4 x 2
    int m0 = blockIdx.y * 128, n0 = blockIdx.x * 128;
    uint32_t sA = smem_u32(&As[0][0]);
    uint32_t sB = smem_u32(&Bs[0][0]);

    // cp.async chunk mapping: 512 16B-chunks per tile, 2 per thread
    int r0c = tid >> 1, c0c = (tid & 1) * 2;   // rows tid/2, chunk cols {0,1} & {2,3}

    float acc[2][8][4];
    #pragma unroll
    for (int i = 0; i < 2; i++)
        #pragma unroll
        for (int j = 0; j < 8; j++)
            #pragma unroll
            for (int c = 0; c < 4; c++) acc[i][j][c] = 0.f;

    int NT = K / BK;

    auto load_tile = [&](int buf, int k0) {
        #pragma unroll
        for (int j = 0; j < 2; j++) {
            int r = r0c, c = c0c + j;
            uint32_t so = (uint32_t)(r * LDS_ + c * 8) * 2;
            cpa16(sA + buf * (128 * LDS_ * 2) + so,
                  (const void*)(A + (size_t)(m0 + r) * K + k0 + c * 8));
            cpa16(sB + buf * (128 * LDS_ * 2) + so,
                  (const void*)(B + (size_t)(n0 + r) * K + k0 + c * 8));
        }
    };

    load_tile(0, 0);
    CP_COMMIT();

    // ldmatrix per-lane offsets
    int lr = lane & 15;            // row within 16-row tile
    int lc = (lane >> 4) * 8;      // 8-col half select

    for (int kt = 0; kt < NT; kt++) {
        if (kt + 1 < NT) { load_tile((kt + 1) & 1, (kt + 1) * BK); CP_COMMIT(); CP_WAIT(1); }
        else             { CP_WAIT(0); }
        __syncthreads();

        int buf = kt & 1;
        uint32_t bufA = sA + buf * (128 * LDS_ * 2);
        uint32_t bufB = sB + buf * (128 * LDS_ * 2);

        #pragma unroll
        for (int s = 0; s < 2; s++) {          // two k16 steps in BK=32
            uint32_t a[2][4];
            #pragma unroll
            for (int i = 0; i < 2; i++) {
                uint32_t ad = bufA +
                    (uint32_t)((wm * 32 + i * 16 + lr) * LDS_ + s * 16 + lc) * 2;
                ldm_x4(a[i][0], a[i][1], a[i][2], a[i][3], ad);
            }
            uint32_t b[4][4];
            #pragma unroll
            for (int p = 0; p < 4; p++) {
                uint32_t bd = bufB +
                    (uint32_t)((wn * 64 + p * 16 + lr) * LDS_ + s * 16 + lc) * 2;
                ldm_x4(b[p][0], b[p][1], b[p][2], b[p][3], bd);
            }
            #pragma unroll
            for (int i = 0; i < 2; i++)
                #pragma unroll
                for (int p = 0; p < 4; p++) {
                    mma16816(acc[i][2 * p],     a[i], b[p][0], b[p][2]);
                    mma16816(acc[i][2 * p + 1], a[i], b[p][1], b[p][3]);
                }
        }
        __syncthreads();
    }

    // Epilogue: c0,c1 -> (row, col..col+1); c2,c3 -> (row+8, ...)
    int cr = lane >> 2, cc = (lane & 3) * 2;
    #pragma unroll
    for (int i = 0; i < 2; i++) {
        int rowA = m0 + wm * 32 + i * 16 + cr;
        #pragma unroll
        for (int j = 0; j < 8; j++) {
            int col = n0 + wn * 64 + j * 8 + cc;
            float2 v0 = make_float2(acc[i][j][0], acc[i][j][1]);
            float2 v1 = make_float2(acc[i][j][2], acc[i][j][3]);
            *(float2*)&C[(size_t)rowA * N + col]       = v0;
            *(float2*)&C[(size_t)(rowA + 8) * N + col] = v1;
        }
    }
}

// ---------------------------------------------------------------------------
// Fused RMSNorm + RoPE (+ optional gain). One block per (token-row, head).
// ---------------------------------------------------------------------------
__global__ void rmsrope_kernel(float* __restrict__ buf, int nheads,
                               const float* __restrict__ gain)
{
    int bt = blockIdx.x, h = blockIdx.y, tid = threadIdx.x; // 128 threads
    float* row = buf + (size_t)bt * nheads * D + h * D;
    float x = row[tid];
    float ss = x * x;
    #pragma unroll
    for (int o = 16; o; o >>= 1) ss += __shfl_xor_sync(0xffffffffu, ss, o);
    __shared__ float ws[4];
    __shared__ float sh[128];
    if ((tid & 31) == 0) ws[tid >> 5] = ss;
    __syncthreads();
    float total = ws[0] + ws[1] + ws[2] + ws[3];
    float rn = rsqrtf(total * (1.0f / 128.0f) + 1.1920929e-7f);
    sh[tid] = x * rn;
    __syncthreads();
    if (tid < HALF) {
        int t = bt % T;
        float c = g_cos[t * HALF + tid], s = g_sin[t * HALF + tid];
        float gv = gain ? gain[h] : 1.0f;
        float x1 = sh[tid], x2 = sh[tid + HALF];
        row[tid]        = (x1 * c + x2 * s) * gv;
        row[tid + HALF] = (x2 * c - x1 * s) * gv;
    }
}

// ---------------------------------------------------------------------------
// Flash attention (causal, GQA) — fp32 (unchanged).
// ---------------------------------------------------------------------------
constexpr int QS_STR = 129;
constexpr int PS_STR = 65;
constexpr size_t ATTN_SMEM = (size_t)(3 * 64 * QS_STR + 64 * PS_STR) * sizeof(float);

__global__ void __launch_bounds__(256) attn_kernel()
{
    extern __shared__ float sm[];
    float* Qs = sm;
    float* Ks = Qs + 64 * QS_STR;
    float* Vs = Ks + 64 * QS_STR;
    float* Ps = Vs + 64 * QS_STR;

    int qt = blockIdx.x, h = blockIdx.y, b = blockIdx.z;
    int hk = h / G;
    int tid = threadIdx.x;
    int tr = tid >> 4, tc = tid & 15;
    int qb = qt * 64;
    const float scale = 0.08838834764831845f;

    const float* qptr = g_q + (size_t)(b * T + qb) * DIM + h * D;
    for (int i = tid; i < 64 * 128; i += 256) {
        int rr = i >> 7, cc = i & 127;
        Qs[rr * QS_STR + cc] = qptr[(size_t)rr * DIM + cc];
    }

    float m[4], l[4], acc[4][8];
    #pragma unroll
    for (int i = 0; i < 4; i++) {
        m[i] = -1e30f; l[i] = 0.f;
        #pragma unroll
        for (int k = 0; k < 8; k++) acc[i][k] = 0.f;
    }

    for (int j = 0; j <= qt; j++) {
        int kb = j * 64;
        const float* kp = g_k + (size_t)(b * T + kb) * KVD + hk * D;
        const float* vp = g_v + (size_t)(b * T + kb) * KVD + hk * D;
        __syncthreads();
        for (int i = tid; i < 64 * 128; i += 256) {
            int rr = i >> 7, cc = i & 127;
            Ks[rr * QS_STR + cc] = kp[(size_t)rr * KVD + cc];
            Vs[rr * QS_STR + cc] = vp[(size_t)rr * KVD + cc];
        }
        __syncthreads();

        float s[4][4];
        #pragma unroll
        for (int i = 0; i < 4; i++)
            #pragma unroll
            for (int jj = 0; jj < 4; jj++) s[i][jj] = 0.f;

        #pragma unroll 4
        for (int d = 0; d < 128; d++) {
            float qv[4], kv[4];
            #pragma unroll
            for (int i = 0; i < 4; i++)  qv[i]  = Qs[(i * 16 + tr) * QS_STR + d];
            #pragma unroll
            for (int jj = 0; jj < 4; jj++) kv[jj] = Ks[(jj * 16 + tc) * QS_STR + d];
            #pragma unroll
            for (int i = 0; i < 4; i++)
                #pragma unroll
                for (int jj = 0; jj < 4; jj++)
                    s[i][jj] += qv[i] * kv[jj];
        }

        bool diag = (j == qt);
        #pragma unroll
        for (int i = 0; i < 4; i++)
            #pragma unroll
            for (int jj = 0; jj < 4; jj++) {
                float v = s[i][jj] * scale;
                if (diag && (jj * 16 + tc) > (i * 16 + tr)) v = -1e30f;
                s[i][jj] = v;
            }

        #pragma unroll
        for (int i = 0; i < 4; i++) {
            float mx = fmaxf(fmaxf(s[i][0], s[i][1]), fmaxf(s[i][2], s[i][3]));
            #pragma unroll
            for (int o = 1; o < 16; o <<= 1)
                mx = fmaxf(mx, __shfl_xor_sync(0xffffffffu, mx, o));
            float mn = fmaxf(m[i], mx);
            float f = expf(m[i] - mn);
            float sum = 0.f;
            #pragma unroll
            for (int jj = 0; jj < 4; jj++) {
                float p = expf(s[i][jj] - mn);
                s[i][jj] = p;
                sum += p;
            }
            #pragma unroll
            for (int o = 1; o < 16; o <<= 1)
                sum += __shfl_xor_sync(0xffffffffu, sum, o);
            l[i] = l[i] * f + sum;
            m[i] = mn;
            #pragma unroll
            for (int k = 0; k < 8; k++) acc[i][k] *= f;
            #pragma unroll
            for (int jj = 0; jj < 4; jj++)
                Ps[(i * 16 + tr) * PS_STR + jj * 16 + tc] = s[i][jj];
        }
        __syncthreads();

        #pragma unroll 2
        for (int c = 0; c < 64; c++) {
            float pv[4], vv[8];
            #pragma unroll
            for (int i = 0; i < 4; i++) pv[i] = Ps[(i * 16 + tr) * PS_STR + c];
            #pragma unroll
            for (int k = 0; k < 8; k++) vv[k] = Vs[c * QS_STR + k * 16 + tc];
            #pragma unroll
            for (int i = 0; i < 4; i++)
                #pragma unroll
                for (int k = 0; k < 8; k++)
                    acc[i][k] += pv[i] * vv[k];
        }
    }

    float* yp = g_y + (size_t)(b * T + qb) * DIM + h * D;
    #pragma unroll
    for (int i = 0; i < 4; i++) {
        float inv = 1.0f / l[i];
        #pragma unroll
        for (int k = 0; k < 8; k++)
            yp[(size_t)(i * 16 + tr) * DIM + k * 16 + tc] = acc[i][k] * inv;
    }
}

// ---------------------------------------------------------------------------
extern "C" void kernel_launch(void* const* d_in, const int* in_sizes, int n_in,
                              void* d_out, int out_size)
{
    const float* x  = (const float*)d_in[0];
    const float* Wq = (const float*)d_in[1];
    const float* Wk = (const float*)d_in[2];
    const float* Wv = (const float*)d_in[3];
    const float* Wp = (const float*)d_in[4];
    const float* qg = (const float*)d_in[5];
    float* out = (float*)d_out;

    float *qp, *kp, *vp, *yp;
    __nv_bfloat16 *xe, *ye, *wqe, *wke, *wve, *wpe;
    cudaGetSymbolAddress((void**)&qp,  g_q);
    cudaGetSymbolAddress((void**)&kp,  g_k);
    cudaGetSymbolAddress((void**)&vp,  g_v);
    cudaGetSymbolAddress((void**)&yp,  g_y);
    cudaGetSymbolAddress((void**)&xe,  g_xe);
    cudaGetSymbolAddress((void**)&ye,  g_ye);
    cudaGetSymbolAddress((void**)&wqe, g_wqe);
    cudaGetSymbolAddress((void**)&wke, g_wke);
    cudaGetSymbolAddress((void**)&wve, g_wve);
    cudaGetSymbolAddress((void**)&wpe, g_wpe);

    cudaFuncSetAttribute(attn_kernel, cudaFuncAttributeMaxDynamicSharedMemorySize,
                         (int)ATTN_SMEM);

    rope_table_kernel<<<(T * HALF + 255) / 256, 256>>>();

    // bf16x3 operand splits
    split_kernel<<<((size_t)BT  * DIM + 255) / 256, 256>>>(x,  xe,  BT,  DIM, 0);
    split_kernel<<<((size_t)DIM * DIM + 255) / 256, 256>>>(Wq, wqe, DIM, DIM, 1);
    split_kernel<<<((size_t)KVD * DIM + 255) / 256, 256>>>(Wk, wke, KVD, DIM, 1);
    split_kernel<<<((size_t)KVD * DIM + 255) / 256, 256>>>(Wv, wve, KVD, DIM, 1);
    split_kernel<<<((size_t)DIM * DIM + 255) / 256, 256>>>(Wp, wpe, DIM, DIM, 1);

    // Projections via HMMA (mma.sync bf16, bf16x3 accuracy)
    gemm_mma<<<dim3(DIM / 128, BT / 128), 256>>>(xe, wqe, qp, BT, DIM, K3);
    gemm_mma<<<dim3(KVD / 128, BT / 128), 256>>>(xe, wke, kp, BT, KVD, K3);
    gemm_mma<<<dim3(KVD / 128, BT / 128), 256>>>(xe, wve, vp, BT, KVD, K3);

    rmsrope_kernel<<<dim3(BT, H),   128>>>(qp, H,   qg);
    rmsrope_kernel<<<dim3(BT, HKV), 128>>>(kp, HKV, nullptr);

    attn_kernel<<<dim3(T / 64, H, Bc), 256, ATTN_SMEM>>>();

    // Output projection
    split_kernel<<<((size_t)BT * DIM + 255) / 256, 256>>>(yp, ye, BT, DIM, 0);
    gemm_mma<<<dim3(DIM / 128, BT / 128), 256>>>(ye, wpe, out, BT, DIM, K3);
}

// round 5
// speedup vs baseline: 2.2409x; 1.5393x over previous
#include <cuda_runtime.h>
#include <cuda_bf16.h>
#include <math.h>
#include <stdint.h>

// Problem constants
constexpr int Bc   = 2;
constexpr int T    = 2048;
constexpr int DIM  = 2048;
constexpr int H    = 16;
constexpr int HKV  = 4;
constexpr int D    = 128;
constexpr int HALF = 64;
constexpr int G    = 4;
constexpr int BT   = Bc * T;   // 4096
constexpr int KVD  = HKV * D;  // 512
constexpr int K3   = 3 * DIM;  // 6144 (bf16x3 extended K)

// Scratch (__device__ globals; allocation-free rule)
__device__ float g_q[(size_t)BT * DIM];
__device__ float g_k[(size_t)BT * KVD];
__device__ float g_v[(size_t)BT * KVD];
__device__ float g_cos[T * HALF];
__device__ float g_sin[T * HALF];
__device__ __nv_bfloat16 g_xe [(size_t)BT  * K3];
__device__ __nv_bfloat16 g_ye [(size_t)BT  * K3];
__device__ __nv_bfloat16 g_wqe[(size_t)DIM * K3];
__device__ __nv_bfloat16 g_wke[(size_t)KVD * K3];
__device__ __nv_bfloat16 g_wve[(size_t)KVD * K3];
__device__ __nv_bfloat16 g_wpe[(size_t)DIM * K3];
// hi/lo split operands for tensor-core attention
__device__ __nv_bfloat16 g_qh[(size_t)BT * DIM];
__device__ __nv_bfloat16 g_ql[(size_t)BT * DIM];
__device__ __nv_bfloat16 g_kh[(size_t)BT * KVD];
__device__ __nv_bfloat16 g_kl[(size_t)BT * KVD];
__device__ __nv_bfloat16 g_vh[(size_t)BT * KVD];
__device__ __nv_bfloat16 g_vl[(size_t)BT * KVD];

// ---------------------------------------------------------------------------
// Helpers (sm_80-level features only)
// ---------------------------------------------------------------------------
__device__ __forceinline__ uint32_t smem_u32(const void* p) {
    uint32_t a;
    asm("{ .reg .u64 t; cvta.to.shared.u64 t, %1; cvt.u32.u64 %0, t; }"
        : "=r"(a) : "l"(p));
    return a;
}
__device__ __forceinline__ void cpa16(uint32_t dst, const void* g) {
    asm volatile("cp.async.cg.shared.global [%0], [%1], 16;"
                 :: "r"(dst), "l"(g) : "memory");
}
#define CP_COMMIT() asm volatile("cp.async.commit_group;" ::: "memory")
#define CP_WAIT(n)  asm volatile("cp.async.wait_group %0;" :: "n"(n) : "memory")

__device__ __forceinline__ void ldm_x4(uint32_t* r, uint32_t a) {
    asm volatile("ldmatrix.sync.aligned.m8n8.x4.shared.b16 {%0,%1,%2,%3}, [%4];"
                 : "=r"(r[0]), "=r"(r[1]), "=r"(r[2]), "=r"(r[3]) : "r"(a));
}
__device__ __forceinline__ void ldm_x4t(uint32_t* r, uint32_t a) {
    asm volatile("ldmatrix.sync.aligned.m8n8.x4.trans.shared.b16 {%0,%1,%2,%3}, [%4];"
                 : "=r"(r[0]), "=r"(r[1]), "=r"(r[2]), "=r"(r[3]) : "r"(a));
}
__device__ __forceinline__ void mma16816(float* c, const uint32_t* a,
                                         uint32_t b0, uint32_t b1) {
    asm volatile(
        "mma.sync.aligned.m16n8k16.row.col.f32.bf16.bf16.f32 "
        "{%0,%1,%2,%3}, {%4,%5,%6,%7}, {%8,%9}, {%0,%1,%2,%3};"
        : "+f"(c[0]), "+f"(c[1]), "+f"(c[2]), "+f"(c[3])
        : "r"(a[0]), "r"(a[1]), "r"(a[2]), "r"(a[3]), "r"(b0), "r"(b1));
}
__device__ __forceinline__ float ex2(float x) {
    float r;
    asm("ex2.approx.f32 %0, %1;" : "=f"(r) : "f"(x));
    return r;
}
__device__ __forceinline__ uint32_t pack_bf16x2(float lo, float hi) {
    uint32_t d;
    asm("cvt.rn.bf16x2.f32 %0, %1, %2;" : "=r"(d) : "f"(hi), "f"(lo));
    return d;
}

// ---------------------------------------------------------------------------
// RoPE tables (float64 to match numpy). T>TRAIN_LEN: base = 10000 * 2^(D/(D-2)).
// ---------------------------------------------------------------------------
__global__ void rope_table_kernel() {
    int idx = blockIdx.x * blockDim.x + threadIdx.x;
    if (idx >= T * HALF) return;
    int t = idx / HALF, i = idx % HALF;
    double base = 10000.0 * pow(2.0, 128.0 / 126.0);
    double inv  = pow(base, -(2.0 * (double)i) / 128.0);
    double f    = (double)t * inv;
    g_cos[idx] = (float)cos(f);
    g_sin[idx] = (float)sin(f);
}

// ---------------------------------------------------------------------------
// bf16x3 split: fp32 [rows, K] -> bf16 [rows, 3K].
// mode 0 (A side): [hi | lo | hi]    mode 1 (B side): [hi | hi | lo]
// ---------------------------------------------------------------------------
__global__ void split_kernel(const float* __restrict__ src,
                             __nv_bfloat16* __restrict__ dst,
                             int rows, int K, int mode) {
    long long idx = (long long)blockIdx.x * blockDim.x + threadIdx.x;
    long long total = (long long)rows * K;
    if (idx >= total) return;
    int r = (int)(idx / K), k = (int)(idx % K);
    float x = src[idx];
    __nv_bfloat16 h = __float2bfloat16(x);
    __nv_bfloat16 l = __float2bfloat16(x - __bfloat162float(h));
    __nv_bfloat16* row = dst + (size_t)r * (3 * K);
    if (mode == 0) { row[k] = h; row[K + k] = l; row[2 * K + k] = h; }
    else           { row[k] = h; row[K + k] = h; row[2 * K + k] = l; }
}

// Elementwise hi/lo split (for V)
__global__ void hl_split(const float* __restrict__ src,
                         __nv_bfloat16* __restrict__ dh,
                         __nv_bfloat16* __restrict__ dl, long long n) {
    long long i = (long long)blockIdx.x * blockDim.x + threadIdx.x;
    if (i >= n) return;
    float x = src[i];
    __nv_bfloat16 h = __float2bfloat16(x);
    dh[i] = h;
    dl[i] = __float2bfloat16(x - __bfloat162float(h));
}

// ---------------------------------------------------------------------------
// bf16 NT GEMM via mma.sync (validated in R3): C = A * B^T, fp32 acc.
// CTA 128x128, BK=32, 8 warps (4x2), warp tile 32x64.
// ---------------------------------------------------------------------------
constexpr int BK  = 32;
constexpr int LDS_ = BK + 8;

__global__ void __launch_bounds__(256, 2) gemm_mma(
    const __nv_bfloat16* __restrict__ A, const __nv_bfloat16* __restrict__ B,
    float* __restrict__ C, int M, int N, int K)
{
    __shared__ __nv_bfloat16 As[2][128 * LDS_];
    __shared__ __nv_bfloat16 Bs[2][128 * LDS_];

    int tid = threadIdx.x, lane = tid & 31, wid = tid >> 5;
    int wm = wid & 3, wn = wid >> 2;
    int m0 = blockIdx.y * 128, n0 = blockIdx.x * 128;
    uint32_t sA = smem_u32(&As[0][0]);
    uint32_t sB = smem_u32(&Bs[0][0]);

    int r0c = tid >> 1, c0c = (tid & 1) * 2;

    float acc[2][8][4];
    #pragma unroll
    for (int i = 0; i < 2; i++)
        #pragma unroll
        for (int j = 0; j < 8; j++)
            #pragma unroll
            for (int c = 0; c < 4; c++) acc[i][j][c] = 0.f;

    int NT = K / BK;

    auto load_tile = [&](int buf, int k0) {
        #pragma unroll
        for (int j = 0; j < 2; j++) {
            int r = r0c, c = c0c + j;
            uint32_t so = (uint32_t)(r * LDS_ + c * 8) * 2;
            cpa16(sA + buf * (128 * LDS_ * 2) + so,
                  (const void*)(A + (size_t)(m0 + r) * K + k0 + c * 8));
            cpa16(sB + buf * (128 * LDS_ * 2) + so,
                  (const void*)(B + (size_t)(n0 + r) * K + k0 + c * 8));
        }
    };

    load_tile(0, 0);
    CP_COMMIT();

    int lr = lane & 15;
    int lc = (lane >> 4) * 8;

    for (int kt = 0; kt < NT; kt++) {
        if (kt + 1 < NT) { load_tile((kt + 1) & 1, (kt + 1) * BK); CP_COMMIT(); CP_WAIT(1); }
        else             { CP_WAIT(0); }
        __syncthreads();

        int buf = kt & 1;
        uint32_t bufA = sA + buf * (128 * LDS_ * 2);
        uint32_t bufB = sB + buf * (128 * LDS_ * 2);

        #pragma unroll
        for (int s = 0; s < 2; s++) {
            uint32_t a[2][4];
            #pragma unroll
            for (int i = 0; i < 2; i++) {
                uint32_t ad = bufA +
                    (uint32_t)((wm * 32 + i * 16 + lr) * LDS_ + s * 16 + lc) * 2;
                ldm_x4(a[i], ad);
            }
            uint32_t b[4][4];
            #pragma unroll
            for (int p = 0; p < 4; p++) {
                uint32_t bd = bufB +
                    (uint32_t)((wn * 64 + p * 16 + lr) * LDS_ + s * 16 + lc) * 2;
                ldm_x4(b[p], bd);
            }
            #pragma unroll
            for (int i = 0; i < 2; i++)
                #pragma unroll
                for (int p = 0; p < 4; p++) {
                    mma16816(acc[i][2 * p],     a[i], b[p][0], b[p][2]);
                    mma16816(acc[i][2 * p + 1], a[i], b[p][1], b[p][3]);
                }
        }
        __syncthreads();
    }

    int cr = lane >> 2, cc = (lane & 3) * 2;
    #pragma unroll
    for (int i = 0; i < 2; i++) {
        int rowA = m0 + wm * 32 + i * 16 + cr;
        #pragma unroll
        for (int j = 0; j < 8; j++) {
            int col = n0 + wn * 64 + j * 8 + cc;
            float2 v0 = make_float2(acc[i][j][0], acc[i][j][1]);
            float2 v1 = make_float2(acc[i][j][2], acc[i][j][3]);
            *(float2*)&C[(size_t)rowA * N + col]       = v0;
            *(float2*)&C[(size_t)(rowA + 8) * N + col] = v1;
        }
    }
}

// ---------------------------------------------------------------------------
// Fused RMSNorm + RoPE (+gain) with bf16 hi/lo split output.
// One block per (token-row, head); 128 threads.
// ---------------------------------------------------------------------------
__global__ void rmsrope_split(const float* __restrict__ buf,
                              __nv_bfloat16* __restrict__ oh,
                              __nv_bfloat16* __restrict__ ol,
                              int nheads, const float* __restrict__ gain)
{
    int bt = blockIdx.x, h = blockIdx.y, tid = threadIdx.x;
    const float* row = buf + (size_t)bt * nheads * D + h * D;
    float x = row[tid];
    float ss = x * x;
    #pragma unroll
    for (int o = 16; o; o >>= 1) ss += __shfl_xor_sync(0xffffffffu, ss, o);
    __shared__ float ws[4];
    __shared__ float sh[128];
    if ((tid & 31) == 0) ws[tid >> 5] = ss;
    __syncthreads();
    float total = ws[0] + ws[1] + ws[2] + ws[3];
    float rn = rsqrtf(total * (1.0f / 128.0f) + 1.1920929e-7f);
    sh[tid] = x * rn;
    __syncthreads();
    if (tid < HALF) {
        int t = bt % T;
        float c = g_cos[t * HALF + tid], s = g_sin[t * HALF + tid];
        float gv = gain ? gain[h] : 1.0f;
        float x1 = sh[tid], x2 = sh[tid + HALF];
        float v1 = (x1 * c + x2 * s) * gv;
        float v2 = (x2 * c - x1 * s) * gv;
        size_t o = (size_t)bt * nheads * D + h * D;
        __nv_bfloat16 h1 = __float2bfloat16(v1);
        __nv_bfloat16 h2 = __float2bfloat16(v2);
        oh[o + tid]        = h1;
        oh[o + tid + HALF] = h2;
        ol[o + tid]        = __float2bfloat16(v1 - __bfloat162float(h1));
        ol[o + tid + HALF] = __float2bfloat16(v2 - __bfloat162float(h2));
    }
}

// ---------------------------------------------------------------------------
// Tensor-core flash attention (causal, GQA), bf16x3 accuracy.
// CTA: 128 queries x (64-key tiles), 8 warps; warp owns a 16-row stripe.
// S = Qh*Kh' + Ql*Kh' + Qh*Kl'; PV = Ph*Vh + Pl*Vh + Ph*Vl.
// Output written directly in ye's [hi|lo|hi] extended bf16 layout.
// ---------------------------------------------------------------------------
constexpr int LQ = 136;                       // padded row (bf16 elems)
constexpr int QTILE_B = 128 * LQ * 2;         // 34816 bytes
constexpr int KTILE_B = 64 * LQ * 2;          // 17408 bytes
constexpr size_t ATTN2_SMEM = (size_t)QTILE_B * 2   // Qh, Ql
                            + (size_t)KTILE_B * 2 * 2  // Kh+Kl x 2 buffers
                            + (size_t)QTILE_B * 2;  // [Vh;Vl] x 2 buffers  = 208896

__global__ void __launch_bounds__(256, 1) attn_tc(
    const __nv_bfloat16* __restrict__ Qhp, const __nv_bfloat16* __restrict__ Qlp,
    const __nv_bfloat16* __restrict__ Khp, const __nv_bfloat16* __restrict__ Klp,
    const __nv_bfloat16* __restrict__ Vhp, const __nv_bfloat16* __restrict__ Vlp,
    __nv_bfloat16* __restrict__ Ye)
{
    extern __shared__ __align__(128) char smem[];
    uint32_t sb = smem_u32(smem);
    const int qi = blockIdx.x, h = blockIdx.y, b = blockIdx.z;
    const int hk = h / G;
    const int tid = threadIdx.x, lane = tid & 31, w = tid >> 5;
    const int qb = qi * 128;
    const int jmax = 2 * qi + 1;
    const int lr = lane & 15, lc = (lane >> 4) * 8;
    const float LS = (float)(1.4426950408889634 * 0.08838834764831845); // log2e/sqrt(D)

    const uint32_t QH = sb;
    const uint32_t QL = sb + QTILE_B;
    const uint32_t KB0 = sb + 2 * QTILE_B;            // per buffer: Kh then Kl
    const uint32_t VB0 = KB0 + 2 * (2 * KTILE_B);     // per buffer: Vh rows 0-63, Vl rows 64-127

    // ---- Q load (both hi and lo), in group with tile 0
    {
        const __nv_bfloat16* qh_p = Qhp + (size_t)(b * T + qb) * DIM + h * D;
        const __nv_bfloat16* ql_p = Qlp + (size_t)(b * T + qb) * DIM + h * D;
        #pragma unroll
        for (int c = tid; c < 2048; c += 256) {
            int r = c >> 4, cc = c & 15;
            uint32_t so = (uint32_t)(r * LQ + cc * 8) * 2;
            cpa16(QH + so, qh_p + (size_t)r * DIM + cc * 8);
            cpa16(QL + so, ql_p + (size_t)r * DIM + cc * 8);
        }
    }

    auto load_kv = [&](int j, int buf) {
        int kb = j * 64;
        const __nv_bfloat16* khp = Khp + (size_t)(b * T + kb) * KVD + hk * D;
        const __nv_bfloat16* klp = Klp + (size_t)(b * T + kb) * KVD + hk * D;
        const __nv_bfloat16* vhp = Vhp + (size_t)(b * T + kb) * KVD + hk * D;
        const __nv_bfloat16* vlp = Vlp + (size_t)(b * T + kb) * KVD + hk * D;
        uint32_t kh_s = KB0 + buf * (2 * KTILE_B);
        uint32_t kl_s = kh_s + KTILE_B;
        uint32_t v_s  = VB0 + buf * QTILE_B;
        #pragma unroll
        for (int c = tid; c < 1024; c += 256) {
            int r = c >> 4, cc = c & 15;
            uint32_t so = (uint32_t)(r * LQ + cc * 8) * 2;
            size_t go = (size_t)r * KVD + cc * 8;
            cpa16(kh_s + so, khp + go);
            cpa16(kl_s + so, klp + go);
            cpa16(v_s + so, vhp + go);
            cpa16(v_s + (uint32_t)(64 * LQ * 2) + so, vlp + go);
        }
    };

    load_kv(0, 0);
    CP_COMMIT();

    float y[16][4];
    #pragma unroll
    for (int t = 0; t < 16; t++)
        #pragma unroll
        for (int c = 0; c < 4; c++) y[t][c] = 0.f;
    float m0 = -INFINITY, m1 = -INFINITY, l0 = 0.f, l1 = 0.f;

    for (int j = 0; j <= jmax; j++) {
        if (j < jmax) { load_kv(j + 1, (j + 1) & 1); CP_COMMIT(); CP_WAIT(1); }
        else          { CP_WAIT(0); }
        __syncthreads();

        // fully-masked warp-tile skip (keys all above this warp's rows)
        bool active = (64 * j) <= (qb + w * 16 + 15);
        if (active) {
            int buf = j & 1;
            uint32_t kh_s = KB0 + buf * (2 * KTILE_B);
            uint32_t kl_s = kh_s + KTILE_B;
            uint32_t v_s  = VB0 + buf * QTILE_B;

            // ---- S = Qh*Kh' + Ql*Kh' + Qh*Kl'
            float s[8][4];
            #pragma unroll
            for (int t = 0; t < 8; t++)
                #pragma unroll
                for (int c = 0; c < 4; c++) s[t][c] = 0.f;

            #pragma unroll
            for (int ks = 0; ks < 8; ks++) {
                uint32_t aqh[4], aql[4], bb[4][4];
                uint32_t ao = (uint32_t)((w * 16 + lr) * LQ + ks * 16 + lc) * 2;
                ldm_x4(aqh, QH + ao);
                ldm_x4(aql, QL + ao);
                #pragma unroll
                for (int nb = 0; nb < 4; nb++)
                    ldm_x4(bb[nb], kh_s + (uint32_t)((nb * 16 + lr) * LQ + ks * 16 + lc) * 2);
                #pragma unroll
                for (int nb = 0; nb < 4; nb++) {
                    mma16816(s[2 * nb],     aqh, bb[nb][0], bb[nb][2]);
                    mma16816(s[2 * nb + 1], aqh, bb[nb][1], bb[nb][3]);
                    mma16816(s[2 * nb],     aql, bb[nb][0], bb[nb][2]);
                    mma16816(s[2 * nb + 1], aql, bb[nb][1], bb[nb][3]);
                }
                #pragma unroll
                for (int nb = 0; nb < 4; nb++)
                    ldm_x4(bb[nb], kl_s + (uint32_t)((nb * 16 + lr) * LQ + ks * 16 + lc) * 2);
                #pragma unroll
                for (int nb = 0; nb < 4; nb++) {
                    mma16816(s[2 * nb],     aqh, bb[nb][0], bb[nb][2]);
                    mma16816(s[2 * nb + 1], aqh, bb[nb][1], bb[nb][3]);
                }
            }

            // ---- scale + causal mask + online softmax (rows r0 and r0+8)
            int r0 = lane >> 2;
            int row0g = qb + w * 16 + r0;
            int row1g = row0g + 8;
            bool need_mask = (64 * j + 63) > row0g;  // conservative per warp-thread
            float mx0 = -INFINITY, mx1 = -INFINITY;
            #pragma unroll
            for (int t = 0; t < 8; t++) {
                int colg = j * 64 + t * 8 + 2 * (lane & 3);
                #pragma unroll
                for (int e = 0; e < 2; e++) {
                    float v0 = s[t][e] * LS;
                    float v1 = s[t][2 + e] * LS;
                    if (need_mask) {
                        if (colg + e > row0g) v0 = -INFINITY;
                        if (colg + e > row1g) v1 = -INFINITY;
                    }
                    s[t][e] = v0; s[t][2 + e] = v1;
                    mx0 = fmaxf(mx0, v0); mx1 = fmaxf(mx1, v1);
                }
            }
            #pragma unroll
            for (int o = 1; o < 4; o <<= 1) {
                mx0 = fmaxf(mx0, __shfl_xor_sync(0xffffffffu, mx0, o));
                mx1 = fmaxf(mx1, __shfl_xor_sync(0xffffffffu, mx1, o));
            }
            float mn0 = fmaxf(m0, mx0), mn1 = fmaxf(m1, mx1);
            float f0 = ex2(m0 - mn0), f1 = ex2(m1 - mn1);
            float sum0 = 0.f, sum1 = 0.f;
            #pragma unroll
            for (int t = 0; t < 8; t++)
                #pragma unroll
                for (int e = 0; e < 2; e++) {
                    float p0 = ex2(s[t][e] - mn0);
                    float p1 = ex2(s[t][2 + e] - mn1);
                    s[t][e] = p0; s[t][2 + e] = p1;
                    sum0 += p0; sum1 += p1;
                }
            #pragma unroll
            for (int o = 1; o < 4; o <<= 1) {
                sum0 += __shfl_xor_sync(0xffffffffu, sum0, o);
                sum1 += __shfl_xor_sync(0xffffffffu, sum1, o);
            }
            l0 = l0 * f0 + sum0; l1 = l1 * f1 + sum1;
            m0 = mn0; m1 = mn1;
            #pragma unroll
            for (int t = 0; t < 16; t++) {
                y[t][0] *= f0; y[t][1] *= f0;
                y[t][2] *= f1; y[t][3] *= f1;
            }

            // ---- PV: Y += Ph*Vh + Pl*Vh + Ph*Vl
            #pragma unroll
            for (int u = 0; u < 4; u++) {
                uint32_t ah[4], al[4];
                {
                    float* pA = s[2 * u];
                    float* pB = s[2 * u + 1];
                    ah[0] = pack_bf16x2(pA[0], pA[1]);
                    ah[1] = pack_bf16x2(pA[2], pA[3]);
                    ah[2] = pack_bf16x2(pB[0], pB[1]);
                    ah[3] = pack_bf16x2(pB[2], pB[3]);
                    #pragma unroll
                    for (int q = 0; q < 4; q++) {
                        float* pp = (q < 2) ? pA : pB;
                        int e = (q & 1) * 2;
                        float hlo = __uint_as_float(ah[q] << 16);
                        float hhi = __uint_as_float(ah[q] & 0xffff0000u);
                        al[q] = pack_bf16x2(pp[e] - hlo, pp[e + 1] - hhi);
                    }
                }
                #pragma unroll
                for (int db = 0; db < 8; db++) {
                    uint32_t bv[4];
                    ldm_x4t(bv, v_s + (uint32_t)((u * 16 + lr) * LQ + db * 16 + lc) * 2);
                    mma16816(y[2 * db],     ah, bv[0], bv[1]);
                    mma16816(y[2 * db + 1], ah, bv[2], bv[3]);
                    mma16816(y[2 * db],     al, bv[0], bv[1]);
                    mma16816(y[2 * db + 1], al, bv[2], bv[3]);
                    ldm_x4t(bv, v_s + (uint32_t)((64 + u * 16 + lr) * LQ + db * 16 + lc) * 2);
                    mma16816(y[2 * db],     ah, bv[0], bv[1]);
                    mma16816(y[2 * db + 1], ah, bv[2], bv[3]);
                }
            }
        }
        __syncthreads();
    }

    // ---- epilogue: write directly in ye extended layout [hi | lo | hi]
    {
        int r0 = lane >> 2;
        float inv0 = 1.0f / l0, inv1 = 1.0f / l1;
        size_t base0 = (size_t)(b * T + qb + w * 16 + r0) * K3 + h * D;
        size_t base1 = base0 + (size_t)8 * K3;
        #pragma unroll
        for (int t = 0; t < 16; t++) {
            int col = t * 8 + 2 * (lane & 3);
            float v00 = y[t][0] * inv0, v01 = y[t][1] * inv0;
            float v10 = y[t][2] * inv1, v11 = y[t][3] * inv1;
            uint32_t h0 = pack_bf16x2(v00, v01);
            uint32_t h1 = pack_bf16x2(v10, v11);
            uint32_t l0p = pack_bf16x2(v00 - __uint_as_float(h0 << 16),
                                       v01 - __uint_as_float(h0 & 0xffff0000u));
            uint32_t l1p = pack_bf16x2(v10 - __uint_as_float(h1 << 16),
                                       v11 - __uint_as_float(h1 & 0xffff0000u));
            *(uint32_t*)&Ye[base0 + col]            = h0;
            *(uint32_t*)&Ye[base0 + DIM + col]      = l0p;
            *(uint32_t*)&Ye[base0 + 2 * DIM + col]  = h0;
            *(uint32_t*)&Ye[base1 + col]            = h1;
            *(uint32_t*)&Ye[base1 + DIM + col]      = l1p;
            *(uint32_t*)&Ye[base1 + 2 * DIM + col]  = h1;
        }
    }
}

// ---------------------------------------------------------------------------
extern "C" void kernel_launch(void* const* d_in, const int* in_sizes, int n_in,
                              void* d_out, int out_size)
{
    const float* x  = (const float*)d_in[0];
    const float* Wq = (const float*)d_in[1];
    const float* Wk = (const float*)d_in[2];
    const float* Wv = (const float*)d_in[3];
    const float* Wp = (const float*)d_in[4];
    const float* qg = (const float*)d_in[5];
    float* out = (float*)d_out;

    float *qp, *kp, *vp;
    __nv_bfloat16 *xe, *ye, *wqe, *wke, *wve, *wpe;
    __nv_bfloat16 *qh, *ql, *kh, *kl, *vh, *vl;
    cudaGetSymbolAddress((void**)&qp,  g_q);
    cudaGetSymbolAddress((void**)&kp,  g_k);
    cudaGetSymbolAddress((void**)&vp,  g_v);
    cudaGetSymbolAddress((void**)&xe,  g_xe);
    cudaGetSymbolAddress((void**)&ye,  g_ye);
    cudaGetSymbolAddress((void**)&wqe, g_wqe);
    cudaGetSymbolAddress((void**)&wke, g_wke);
    cudaGetSymbolAddress((void**)&wve, g_wve);
    cudaGetSymbolAddress((void**)&wpe, g_wpe);
    cudaGetSymbolAddress((void**)&qh,  g_qh);
    cudaGetSymbolAddress((void**)&ql,  g_ql);
    cudaGetSymbolAddress((void**)&kh,  g_kh);
    cudaGetSymbolAddress((void**)&kl,  g_kl);
    cudaGetSymbolAddress((void**)&vh,  g_vh);
    cudaGetSymbolAddress((void**)&vl,  g_vl);

    cudaFuncSetAttribute(attn_tc, cudaFuncAttributeMaxDynamicSharedMemorySize,
                         (int)ATTN2_SMEM);

    rope_table_kernel<<<(T * HALF + 255) / 256, 256>>>();

    // bf16x3 operand splits
    split_kernel<<<((size_t)BT  * DIM + 255) / 256, 256>>>(x,  xe,  BT,  DIM, 0);
    split_kernel<<<((size_t)DIM * DIM + 255) / 256, 256>>>(Wq, wqe, DIM, DIM, 1);
    split_kernel<<<((size_t)KVD * DIM + 255) / 256, 256>>>(Wk, wke, KVD, DIM, 1);
    split_kernel<<<((size_t)KVD * DIM + 255) / 256, 256>>>(Wv, wve, KVD, DIM, 1);
    split_kernel<<<((size_t)DIM * DIM + 255) / 256, 256>>>(Wp, wpe, DIM, DIM, 1);

    // Projections via HMMA
    gemm_mma<<<dim3(DIM / 128, BT / 128), 256>>>(xe, wqe, qp, BT, DIM, K3);
    gemm_mma<<<dim3(KVD / 128, BT / 128), 256>>>(xe, wke, kp, BT, KVD, K3);
    gemm_mma<<<dim3(KVD / 128, BT / 128), 256>>>(xe, wve, vp, BT, KVD, K3);

    // RMSNorm + RoPE (+gain) fused with hi/lo split; V split elementwise
    rmsrope_split<<<dim3(BT, H),   128>>>(qp, qh, ql, H,   qg);
    rmsrope_split<<<dim3(BT, HKV), 128>>>(kp, kh, kl, HKV, nullptr);
    hl_split<<<((size_t)BT * KVD + 255) / 256, 256>>>(vp, vh, vl, (long long)BT * KVD);

    // Tensor-core attention; writes ye in extended [hi|lo|hi] layout
    attn_tc<<<dim3(T / 128, H, Bc), 256, ATTN2_SMEM>>>(qh, ql, kh, kl, vh, vl, ye);

    // Output projection
    gemm_mma<<<dim3(DIM / 128, BT / 128), 256>>>(ye, wpe, out, BT, DIM, K3);
}

// round 6
// speedup vs baseline: 2.2493x; 1.0037x over previous
#include <cuda_runtime.h>
#include <cuda_bf16.h>
#include <math.h>
#include <stdint.h>

// Problem constants
constexpr int Bc   = 2;
constexpr int T    = 2048;
constexpr int DIM  = 2048;
constexpr int H    = 16;
constexpr int HKV  = 4;
constexpr int D    = 128;
constexpr int HALF = 64;
constexpr int G    = 4;
constexpr int BT   = Bc * T;   // 4096
constexpr int KVD  = HKV * D;  // 512
constexpr int K3   = 3 * DIM;  // 6144 (bf16x3 extended K)

// Scratch (__device__ globals; allocation-free rule)
__device__ float g_q[(size_t)BT * DIM];
__device__ float g_k[(size_t)BT * KVD];
__device__ float g_v[(size_t)BT * KVD];
__device__ float g_cos[T * HALF];
__device__ float g_sin[T * HALF];
__device__ __nv_bfloat16 g_xe [(size_t)BT  * K3];
__device__ __nv_bfloat16 g_ye [(size_t)BT  * K3];
__device__ __nv_bfloat16 g_wqe[(size_t)DIM * K3];
__device__ __nv_bfloat16 g_wke[(size_t)KVD * K3];
__device__ __nv_bfloat16 g_wve[(size_t)KVD * K3];
__device__ __nv_bfloat16 g_wpe[(size_t)DIM * K3];
// hi/lo split operands for tensor-core attention
__device__ __nv_bfloat16 g_qh[(size_t)BT * DIM];
__device__ __nv_bfloat16 g_ql[(size_t)BT * DIM];
__device__ __nv_bfloat16 g_kh[(size_t)BT * KVD];
__device__ __nv_bfloat16 g_kl[(size_t)BT * KVD];
__device__ __nv_bfloat16 g_vh[(size_t)BT * KVD];
__device__ __nv_bfloat16 g_vl[(size_t)BT * KVD];

// ---------------------------------------------------------------------------
// Helpers (sm_80-level features only)
// ---------------------------------------------------------------------------
__device__ __forceinline__ uint32_t smem_u32(const void* p) {
    uint32_t a;
    asm("{ .reg .u64 t; cvta.to.shared.u64 t, %1; cvt.u32.u64 %0, t; }"
        : "=r"(a) : "l"(p));
    return a;
}
__device__ __forceinline__ void cpa16(uint32_t dst, const void* g) {
    asm volatile("cp.async.cg.shared.global [%0], [%1], 16;"
                 :: "r"(dst), "l"(g) : "memory");
}
#define CP_COMMIT() asm volatile("cp.async.commit_group;" ::: "memory")
#define CP_WAIT(n)  asm volatile("cp.async.wait_group %0;" :: "n"(n) : "memory")

__device__ __forceinline__ void ldm_x4(uint32_t* r, uint32_t a) {
    asm volatile("ldmatrix.sync.aligned.m8n8.x4.shared.b16 {%0,%1,%2,%3}, [%4];"
                 : "=r"(r[0]), "=r"(r[1]), "=r"(r[2]), "=r"(r[3]) : "r"(a));
}
__device__ __forceinline__ void ldm_x4t(uint32_t* r, uint32_t a) {
    asm volatile("ldmatrix.sync.aligned.m8n8.x4.trans.shared.b16 {%0,%1,%2,%3}, [%4];"
                 : "=r"(r[0]), "=r"(r[1]), "=r"(r[2]), "=r"(r[3]) : "r"(a));
}
__device__ __forceinline__ void mma16816(float* c, const uint32_t* a,
                                         uint32_t b0, uint32_t b1) {
    asm volatile(
        "mma.sync.aligned.m16n8k16.row.col.f32.bf16.bf16.f32 "
        "{%0,%1,%2,%3}, {%4,%5,%6,%7}, {%8,%9}, {%0,%1,%2,%3};"
        : "+f"(c[0]), "+f"(c[1]), "+f"(c[2]), "+f"(c[3])
        : "r"(a[0]), "r"(a[1]), "r"(a[2]), "r"(a[3]), "r"(b0), "r"(b1));
}
__device__ __forceinline__ float ex2(float x) {
    float r;
    asm("ex2.approx.f32 %0, %1;" : "=f"(r) : "f"(x));
    return r;
}
__device__ __forceinline__ uint32_t pack_bf16x2(float lo, float hi) {
    uint32_t d;
    asm("cvt.rn.bf16x2.f32 %0, %1, %2;" : "=r"(d) : "f"(hi), "f"(lo));
    return d;
}

// ---------------------------------------------------------------------------
// RoPE tables (float64 to match numpy). T>TRAIN_LEN: base = 10000 * 2^(D/(D-2)).
// ---------------------------------------------------------------------------
__global__ void rope_table_kernel() {
    int idx = blockIdx.x * blockDim.x + threadIdx.x;
    if (idx >= T * HALF) return;
    int t = idx / HALF, i = idx % HALF;
    double base = 10000.0 * pow(2.0, 128.0 / 126.0);
    double inv  = pow(base, -(2.0 * (double)i) / 128.0);
    double f    = (double)t * inv;
    g_cos[idx] = (float)cos(f);
    g_sin[idx] = (float)sin(f);
}

// ---------------------------------------------------------------------------
// bf16x3 split: fp32 [rows, K] -> bf16 [rows, 3K].
// mode 0 (A side): [hi | lo | hi]    mode 1 (B side): [hi | hi | lo]
// ---------------------------------------------------------------------------
__global__ void split_kernel(const float* __restrict__ src,
                             __nv_bfloat16* __restrict__ dst,
                             int rows, int K, int mode) {
    long long idx = (long long)blockIdx.x * blockDim.x + threadIdx.x;
    long long total = (long long)rows * K;
    if (idx >= total) return;
    int r = (int)(idx / K), k = (int)(idx % K);
    float x = src[idx];
    __nv_bfloat16 h = __float2bfloat16(x);
    __nv_bfloat16 l = __float2bfloat16(x - __bfloat162float(h));
    __nv_bfloat16* row = dst + (size_t)r * (3 * K);
    if (mode == 0) { row[k] = h; row[K + k] = l; row[2 * K + k] = h; }
    else           { row[k] = h; row[K + k] = h; row[2 * K + k] = l; }
}

// Elementwise hi/lo split (for V)
__global__ void hl_split(const float* __restrict__ src,
                         __nv_bfloat16* __restrict__ dh,
                         __nv_bfloat16* __restrict__ dl, long long n) {
    long long i = (long long)blockIdx.x * blockDim.x + threadIdx.x;
    if (i >= n) return;
    float x = src[i];
    __nv_bfloat16 h = __float2bfloat16(x);
    dh[i] = h;
    dl[i] = __float2bfloat16(x - __bfloat162float(h));
}

// ---------------------------------------------------------------------------
// bf16 NT GEMM via mma.sync (validated in R3): C = A * B^T, fp32 acc.
// CTA 128x128, BK=32, 8 warps (4x2), warp tile 32x64.
// ---------------------------------------------------------------------------
constexpr int BK  = 32;
constexpr int LDS_ = BK + 8;

__global__ void __launch_bounds__(256, 2) gemm_mma(
    const __nv_bfloat16* __restrict__ A, const __nv_bfloat16* __restrict__ B,
    float* __restrict__ C, int M, int N, int K)
{
    __shared__ __nv_bfloat16 As[2][128 * LDS_];
    __shared__ __nv_bfloat16 Bs[2][128 * LDS_];

    int tid = threadIdx.x, lane = tid & 31, wid = tid >> 5;
    int wm = wid & 3, wn = wid >> 2;
    int m0 = blockIdx.y * 128, n0 = blockIdx.x * 128;
    uint32_t sA = smem_u32(&As[0][0]);
    uint32_t sB = smem_u32(&Bs[0][0]);

    int r0c = tid >> 1, c0c = (tid & 1) * 2;

    float acc[2][8][4];
    #pragma unroll
    for (int i = 0; i < 2; i++)
        #pragma unroll
        for (int j = 0; j < 8; j++)
            #pragma unroll
            for (int c = 0; c < 4; c++) acc[i][j][c] = 0.f;

    int NT = K / BK;

    auto load_tile = [&](int buf, int k0) {
        #pragma unroll
        for (int j = 0; j < 2; j++) {
            int r = r0c, c = c0c + j;
            uint32_t so = (uint32_t)(r * LDS_ + c * 8) * 2;
            cpa16(sA + buf * (128 * LDS_ * 2) + so,
                  (const void*)(A + (size_t)(m0 + r) * K + k0 + c * 8));
            cpa16(sB + buf * (128 * LDS_ * 2) + so,
                  (const void*)(B + (size_t)(n0 + r) * K + k0 + c * 8));
        }
    };

    load_tile(0, 0);
    CP_COMMIT();

    int lr = lane & 15;
    int lc = (lane >> 4) * 8;

    for (int kt = 0; kt < NT; kt++) {
        if (kt + 1 < NT) { load_tile((kt + 1) & 1, (kt + 1) * BK); CP_COMMIT(); CP_WAIT(1); }
        else             { CP_WAIT(0); }
        __syncthreads();

        int buf = kt & 1;
        uint32_t bufA = sA + buf * (128 * LDS_ * 2);
        uint32_t bufB = sB + buf * (128 * LDS_ * 2);

        #pragma unroll
        for (int s = 0; s < 2; s++) {
            uint32_t a[2][4];
            #pragma unroll
            for (int i = 0; i < 2; i++) {
                uint32_t ad = bufA +
                    (uint32_t)((wm * 32 + i * 16 + lr) * LDS_ + s * 16 + lc) * 2;
                ldm_x4(a[i], ad);
            }
            uint32_t b[4][4];
            #pragma unroll
            for (int p = 0; p < 4; p++) {
                uint32_t bd = bufB +
                    (uint32_t)((wn * 64 + p * 16 + lr) * LDS_ + s * 16 + lc) * 2;
                ldm_x4(b[p], bd);
            }
            #pragma unroll
            for (int i = 0; i < 2; i++)
                #pragma unroll
                for (int p = 0; p < 4; p++) {
                    mma16816(acc[i][2 * p],     a[i], b[p][0], b[p][2]);
                    mma16816(acc[i][2 * p + 1], a[i], b[p][1], b[p][3]);
                }
        }
        __syncthreads();
    }

    int cr = lane >> 2, cc = (lane & 3) * 2;
    #pragma unroll
    for (int i = 0; i < 2; i++) {
        int rowA = m0 + wm * 32 + i * 16 + cr;
        #pragma unroll
        for (int j = 0; j < 8; j++) {
            int col = n0 + wn * 64 + j * 8 + cc;
            float2 v0 = make_float2(acc[i][j][0], acc[i][j][1]);
            float2 v1 = make_float2(acc[i][j][2], acc[i][j][3]);
            *(float2*)&C[(size_t)rowA * N + col]       = v0;
            *(float2*)&C[(size_t)(rowA + 8) * N + col] = v1;
        }
    }
}

// ---------------------------------------------------------------------------
// Fused RMSNorm + RoPE (+gain) with bf16 hi/lo split output.
// One block per (token-row, head); 128 threads.
// ---------------------------------------------------------------------------
__global__ void rmsrope_split(const float* __restrict__ buf,
                              __nv_bfloat16* __restrict__ oh,
                              __nv_bfloat16* __restrict__ ol,
                              int nheads, const float* __restrict__ gain)
{
    int bt = blockIdx.x, h = blockIdx.y, tid = threadIdx.x;
    const float* row = buf + (size_t)bt * nheads * D + h * D;
    float x = row[tid];
    float ss = x * x;
    #pragma unroll
    for (int o = 16; o; o >>= 1) ss += __shfl_xor_sync(0xffffffffu, ss, o);
    __shared__ float ws[4];
    __shared__ float sh[128];
    if ((tid & 31) == 0) ws[tid >> 5] = ss;
    __syncthreads();
    float total = ws[0] + ws[1] + ws[2] + ws[3];
    float rn = rsqrtf(total * (1.0f / 128.0f) + 1.1920929e-7f);
    sh[tid] = x * rn;
    __syncthreads();
    if (tid < HALF) {
        int t = bt % T;
        float c = g_cos[t * HALF + tid], s = g_sin[t * HALF + tid];
        float gv = gain ? gain[h] : 1.0f;
        float x1 = sh[tid], x2 = sh[tid + HALF];
        float v1 = (x1 * c + x2 * s) * gv;
        float v2 = (x2 * c - x1 * s) * gv;
        size_t o = (size_t)bt * nheads * D + h * D;
        __nv_bfloat16 h1 = __float2bfloat16(v1);
        __nv_bfloat16 h2 = __float2bfloat16(v2);
        oh[o + tid]        = h1;
        oh[o + tid + HALF] = h2;
        ol[o + tid]        = __float2bfloat16(v1 - __bfloat162float(h1));
        ol[o + tid + HALF] = __float2bfloat16(v2 - __bfloat162float(h2));
    }
}

// ---------------------------------------------------------------------------
// Tensor-core flash attention (causal, GQA), bf16x3 accuracy.
// CTA: 128 queries x (64-key tiles), 8 warps; warp owns a 16-row stripe.
// S = Qh*Kh' + Ql*Kh' + Qh*Kl'; PV = Ph*Vh + Pl*Vh + Ph*Vl.
// Output written directly in ye's [hi|lo|hi] extended bf16 layout.
// ---------------------------------------------------------------------------
constexpr int LQ = 136;                       // padded row (bf16 elems)
constexpr int QTILE_B = 128 * LQ * 2;         // 34816 bytes
constexpr int KTILE_B = 64 * LQ * 2;          // 17408 bytes
constexpr size_t ATTN2_SMEM = (size_t)QTILE_B * 2   // Qh, Ql
                            + (size_t)KTILE_B * 2 * 2  // Kh+Kl x 2 buffers
                            + (size_t)QTILE_B * 2;  // [Vh;Vl] x 2 buffers  = 208896

__global__ void __launch_bounds__(256, 1) attn_tc(
    const __nv_bfloat16* __restrict__ Qhp, const __nv_bfloat16* __restrict__ Qlp,
    const __nv_bfloat16* __restrict__ Khp, const __nv_bfloat16* __restrict__ Klp,
    const __nv_bfloat16* __restrict__ Vhp, const __nv_bfloat16* __restrict__ Vlp,
    __nv_bfloat16* __restrict__ Ye)
{
    extern __shared__ __align__(128) char smem[];
    uint32_t sb = smem_u32(smem);
    const int qi = blockIdx.x, h = blockIdx.y, b = blockIdx.z;
    const int hk = h / G;
    const int tid = threadIdx.x, lane = tid & 31, w = tid >> 5;
    const int qb = qi * 128;
    const int jmax = 2 * qi + 1;
    const int lr = lane & 15, lc = (lane >> 4) * 8;
    const float LS = (float)(1.4426950408889634 * 0.08838834764831845); // log2e/sqrt(D)

    const uint32_t QH = sb;
    const uint32_t QL = sb + QTILE_B;
    const uint32_t KB0 = sb + 2 * QTILE_B;            // per buffer: Kh then Kl
    const uint32_t VB0 = KB0 + 2 * (2 * KTILE_B);     // per buffer: Vh rows 0-63, Vl rows 64-127

    // ---- Q load (both hi and lo), in group with tile 0
    {
        const __nv_bfloat16* qh_p = Qhp + (size_t)(b * T + qb) * DIM + h * D;
        const __nv_bfloat16* ql_p = Qlp + (size_t)(b * T + qb) * DIM + h * D;
        #pragma unroll
        for (int c = tid; c < 2048; c += 256) {
            int r = c >> 4, cc = c & 15;
            uint32_t so = (uint32_t)(r * LQ + cc * 8) * 2;
            cpa16(QH + so, qh_p + (size_t)r * DIM + cc * 8);
            cpa16(QL + so, ql_p + (size_t)r * DIM + cc * 8);
        }
    }

    auto load_kv = [&](int j, int buf) {
        int kb = j * 64;
        const __nv_bfloat16* khp = Khp + (size_t)(b * T + kb) * KVD + hk * D;
        const __nv_bfloat16* klp = Klp + (size_t)(b * T + kb) * KVD + hk * D;
        const __nv_bfloat16* vhp = Vhp + (size_t)(b * T + kb) * KVD + hk * D;
        const __nv_bfloat16* vlp = Vlp + (size_t)(b * T + kb) * KVD + hk * D;
        uint32_t kh_s = KB0 + buf * (2 * KTILE_B);
        uint32_t kl_s = kh_s + KTILE_B;
        uint32_t v_s  = VB0 + buf * QTILE_B;
        #pragma unroll
        for (int c = tid; c < 1024; c += 256) {
            int r = c >> 4, cc = c & 15;
            uint32_t so = (uint32_t)(r * LQ + cc * 8) * 2;
            size_t go = (size_t)r * KVD + cc * 8;
            cpa16(kh_s + so, khp + go);
            cpa16(kl_s + so, klp + go);
            cpa16(v_s + so, vhp + go);
            cpa16(v_s + (uint32_t)(64 * LQ * 2) + so, vlp + go);
        }
    };

    load_kv(0, 0);
    CP_COMMIT();

    float y[16][4];
    #pragma unroll
    for (int t = 0; t < 16; t++)
        #pragma unroll
        for (int c = 0; c < 4; c++) y[t][c] = 0.f;
    float m0 = -INFINITY, m1 = -INFINITY, l0 = 0.f, l1 = 0.f;

    for (int j = 0; j <= jmax; j++) {
        if (j < jmax) { load_kv(j + 1, (j + 1) & 1); CP_COMMIT(); CP_WAIT(1); }
        else          { CP_WAIT(0); }
        __syncthreads();

        // fully-masked warp-tile skip (keys all above this warp's rows)
        bool active = (64 * j) <= (qb + w * 16 + 15);
        if (active) {
            int buf = j & 1;
            uint32_t kh_s = KB0 + buf * (2 * KTILE_B);
            uint32_t kl_s = kh_s + KTILE_B;
            uint32_t v_s  = VB0 + buf * QTILE_B;

            // ---- S = Qh*Kh' + Ql*Kh' + Qh*Kl'
            float s[8][4];
            #pragma unroll
            for (int t = 0; t < 8; t++)
                #pragma unroll
                for (int c = 0; c < 4; c++) s[t][c] = 0.f;

            #pragma unroll
            for (int ks = 0; ks < 8; ks++) {
                uint32_t aqh[4], aql[4], bb[4][4];
                uint32_t ao = (uint32_t)((w * 16 + lr) * LQ + ks * 16 + lc) * 2;
                ldm_x4(aqh, QH + ao);
                ldm_x4(aql, QL + ao);
                #pragma unroll
                for (int nb = 0; nb < 4; nb++)
                    ldm_x4(bb[nb], kh_s + (uint32_t)((nb * 16 + lr) * LQ + ks * 16 + lc) * 2);
                #pragma unroll
                for (int nb = 0; nb < 4; nb++) {
                    mma16816(s[2 * nb],     aqh, bb[nb][0], bb[nb][2]);
                    mma16816(s[2 * nb + 1], aqh, bb[nb][1], bb[nb][3]);
                    mma16816(s[2 * nb],     aql, bb[nb][0], bb[nb][2]);
                    mma16816(s[2 * nb + 1], aql, bb[nb][1], bb[nb][3]);
                }
                #pragma unroll
                for (int nb = 0; nb < 4; nb++)
                    ldm_x4(bb[nb], kl_s + (uint32_t)((nb * 16 + lr) * LQ + ks * 16 + lc) * 2);
                #pragma unroll
                for (int nb = 0; nb < 4; nb++) {
                    mma16816(s[2 * nb],     aqh, bb[nb][0], bb[nb][2]);
                    mma16816(s[2 * nb + 1], aqh, bb[nb][1], bb[nb][3]);
                }
            }

            // ---- scale + causal mask + online softmax (rows r0 and r0+8)
            int r0 = lane >> 2;
            int row0g = qb + w * 16 + r0;
            int row1g = row0g + 8;
            bool need_mask = (64 * j + 63) > row0g;  // conservative per warp-thread
            float mx0 = -INFINITY, mx1 = -INFINITY;
            #pragma unroll
            for (int t = 0; t < 8; t++) {
                int colg = j * 64 + t * 8 + 2 * (lane & 3);
                #pragma unroll
                for (int e = 0; e < 2; e++) {
                    float v0 = s[t][e] * LS;
                    float v1 = s[t][2 + e] * LS;
                    if (need_mask) {
                        if (colg + e > row0g) v0 = -INFINITY;
                        if (colg + e > row1g) v1 = -INFINITY;
                    }
                    s[t][e] = v0; s[t][2 + e] = v1;
                    mx0 = fmaxf(mx0, v0); mx1 = fmaxf(mx1, v1);
                }
            }
            #pragma unroll
            for (int o = 1; o < 4; o <<= 1) {
                mx0 = fmaxf(mx0, __shfl_xor_sync(0xffffffffu, mx0, o));
                mx1 = fmaxf(mx1, __shfl_xor_sync(0xffffffffu, mx1, o));
            }
            float mn0 = fmaxf(m0, mx0), mn1 = fmaxf(m1, mx1);
            float f0 = ex2(m0 - mn0), f1 = ex2(m1 - mn1);
            float sum0 = 0.f, sum1 = 0.f;
            #pragma unroll
            for (int t = 0; t < 8; t++)
                #pragma unroll
                for (int e = 0; e < 2; e++) {
                    float p0 = ex2(s[t][e] - mn0);
                    float p1 = ex2(s[t][2 + e] - mn1);
                    s[t][e] = p0; s[t][2 + e] = p1;
                    sum0 += p0; sum1 += p1;
                }
            #pragma unroll
            for (int o = 1; o < 4; o <<= 1) {
                sum0 += __shfl_xor_sync(0xffffffffu, sum0, o);
                sum1 += __shfl_xor_sync(0xffffffffu, sum1, o);
            }
            l0 = l0 * f0 + sum0; l1 = l1 * f1 + sum1;
            m0 = mn0; m1 = mn1;
            #pragma unroll
            for (int t = 0; t < 16; t++) {
                y[t][0] *= f0; y[t][1] *= f0;
                y[t][2] *= f1; y[t][3] *= f1;
            }

            // ---- PV: Y += Ph*Vh + Pl*Vh + Ph*Vl
            #pragma unroll
            for (int u = 0; u < 4; u++) {
                uint32_t ah[4], al[4];
                {
                    float* pA = s[2 * u];
                    float* pB = s[2 * u + 1];
                    ah[0] = pack_bf16x2(pA[0], pA[1]);
                    ah[1] = pack_bf16x2(pA[2], pA[3]);
                    ah[2] = pack_bf16x2(pB[0], pB[1]);
                    ah[3] = pack_bf16x2(pB[2], pB[3]);
                    #pragma unroll
                    for (int q = 0; q < 4; q++) {
                        float* pp = (q < 2) ? pA : pB;
                        int e = (q & 1) * 2;
                        float hlo = __uint_as_float(ah[q] << 16);
                        float hhi = __uint_as_float(ah[q] & 0xffff0000u);
                        al[q] = pack_bf16x2(pp[e] - hlo, pp[e + 1] - hhi);
                    }
                }
                #pragma unroll
                for (int db = 0; db < 8; db++) {
                    uint32_t bv[4];
                    ldm_x4t(bv, v_s + (uint32_t)((u * 16 + lr) * LQ + db * 16 + lc) * 2);
                    mma16816(y[2 * db],     ah, bv[0], bv[1]);
                    mma16816(y[2 * db + 1], ah, bv[2], bv[3]);
                    mma16816(y[2 * db],     al, bv[0], bv[1]);
                    mma16816(y[2 * db + 1], al, bv[2], bv[3]);
                    ldm_x4t(bv, v_s + (uint32_t)((64 + u * 16 + lr) * LQ + db * 16 + lc) * 2);
                    mma16816(y[2 * db],     ah, bv[0], bv[1]);
                    mma16816(y[2 * db + 1], ah, bv[2], bv[3]);
                }
            }
        }
        __syncthreads();
    }

    // ---- epilogue: write directly in ye extended layout [hi | lo | hi]
    {
        int r0 = lane >> 2;
        float inv0 = 1.0f / l0, inv1 = 1.0f / l1;
        size_t base0 = (size_t)(b * T + qb + w * 16 + r0) * K3 + h * D;
        size_t base1 = base0 + (size_t)8 * K3;
        #pragma unroll
        for (int t = 0; t < 16; t++) {
            int col = t * 8 + 2 * (lane & 3);
            float v00 = y[t][0] * inv0, v01 = y[t][1] * inv0;
            float v10 = y[t][2] * inv1, v11 = y[t][3] * inv1;
            uint32_t h0 = pack_bf16x2(v00, v01);
            uint32_t h1 = pack_bf16x2(v10, v11);
            uint32_t l0p = pack_bf16x2(v00 - __uint_as_float(h0 << 16),
                                       v01 - __uint_as_float(h0 & 0xffff0000u));
            uint32_t l1p = pack_bf16x2(v10 - __uint_as_float(h1 << 16),
                                       v11 - __uint_as_float(h1 & 0xffff0000u));
            *(uint32_t*)&Ye[base0 + col]            = h0;
            *(uint32_t*)&Ye[base0 + DIM + col]      = l0p;
            *(uint32_t*)&Ye[base0 + 2 * DIM + col]  = h0;
            *(uint32_t*)&Ye[base1 + col]            = h1;
            *(uint32_t*)&Ye[base1 + DIM + col]      = l1p;
            *(uint32_t*)&Ye[base1 + 2 * DIM + col]  = h1;
        }
    }
}

// ---------------------------------------------------------------------------
extern "C" void kernel_launch(void* const* d_in, const int* in_sizes, int n_in,
                              void* d_out, int out_size)
{
    const float* x  = (const float*)d_in[0];
    const float* Wq = (const float*)d_in[1];
    const float* Wk = (const float*)d_in[2];
    const float* Wv = (const float*)d_in[3];
    const float* Wp = (const float*)d_in[4];
    const float* qg = (const float*)d_in[5];
    float* out = (float*)d_out;

    float *qp, *kp, *vp;
    __nv_bfloat16 *xe, *ye, *wqe, *wke, *wve, *wpe;
    __nv_bfloat16 *qh, *ql, *kh, *kl, *vh, *vl;
    cudaGetSymbolAddress((void**)&qp,  g_q);
    cudaGetSymbolAddress((void**)&kp,  g_k);
    cudaGetSymbolAddress((void**)&vp,  g_v);
    cudaGetSymbolAddress((void**)&xe,  g_xe);
    cudaGetSymbolAddress((void**)&ye,  g_ye);
    cudaGetSymbolAddress((void**)&wqe, g_wqe);
    cudaGetSymbolAddress((void**)&wke, g_wke);
    cudaGetSymbolAddress((void**)&wve, g_wve);
    cudaGetSymbolAddress((void**)&wpe, g_wpe);
    cudaGetSymbolAddress((void**)&qh,  g_qh);
    cudaGetSymbolAddress((void**)&ql,  g_ql);
    cudaGetSymbolAddress((void**)&kh,  g_kh);
    cudaGetSymbolAddress((void**)&kl,  g_kl);
    cudaGetSymbolAddress((void**)&vh,  g_vh);
    cudaGetSymbolAddress((void**)&vl,  g_vl);

    cudaFuncSetAttribute(attn_tc, cudaFuncAttributeMaxDynamicSharedMemorySize,
                         (int)ATTN2_SMEM);

    rope_table_kernel<<<(T * HALF + 255) / 256, 256>>>();

    // bf16x3 operand splits
    split_kernel<<<((size_t)BT  * DIM + 255) / 256, 256>>>(x,  xe,  BT,  DIM, 0);
    split_kernel<<<((size_t)DIM * DIM + 255) / 256, 256>>>(Wq, wqe, DIM, DIM, 1);
    split_kernel<<<((size_t)KVD * DIM + 255) / 256, 256>>>(Wk, wke, KVD, DIM, 1);
    split_kernel<<<((size_t)KVD * DIM + 255) / 256, 256>>>(Wv, wve, KVD, DIM, 1);
    split_kernel<<<((size_t)DIM * DIM + 255) / 256, 256>>>(Wp, wpe, DIM, DIM, 1);

    // Projections via HMMA
    gemm_mma<<<dim3(DIM / 128, BT / 128), 256>>>(xe, wqe, qp, BT, DIM, K3);
    gemm_mma<<<dim3(KVD / 128, BT / 128), 256>>>(xe, wke, kp, BT, KVD, K3);
    gemm_mma<<<dim3(KVD / 128, BT / 128), 256>>>(xe, wve, vp, BT, KVD, K3);

    // RMSNorm + RoPE (+gain) fused with hi/lo split; V split elementwise
    rmsrope_split<<<dim3(BT, H),   128>>>(qp, qh, ql, H,   qg);
    rmsrope_split<<<dim3(BT, HKV), 128>>>(kp, kh, kl, HKV, nullptr);
    hl_split<<<((size_t)BT * KVD + 255) / 256, 256>>>(vp, vh, vl, (long long)BT * KVD);

    // Tensor-core attention; writes ye in extended [hi|lo|hi] layout
    attn_tc<<<dim3(T / 128, H, Bc), 256, ATTN2_SMEM>>>(qh, ql, kh, kl, vh, vl, ye);

    // Output projection
    gemm_mma<<<dim3(DIM / 128, BT / 128), 256>>>(ye, wpe, out, BT, DIM, K3);
}